// round 3
// baseline (speedup 1.0000x reference)
#include <cuda_runtime.h>

#define G_   1024
#define N_   65536
#define D_   128
#define E_   400000

// Scratch (device globals — no allocations allowed)
__device__ __align__(16) float g_A[G_ * 128];      // graph_and_focus @ W1[0:384] + b1 (64 scorer | 64 type cols)
__device__ __align__(16) float g_C[N_ * 128];      // node @ W1[384:512] + A[n2g[node]] (fused per-node table)
__device__ __align__(16) float g_distC[10 * 128];  // dist_table[d] * W1[512]

// packed f32x2 helpers (full-rate FMA pipe; scalar 3-reg FFMA is half-rate)
__device__ __forceinline__ unsigned long long fma2(unsigned long long a, unsigned long long b,
                                                   unsigned long long c) {
    unsigned long long d;
    asm("fma.rn.f32x2 %0, %1, %2, %3;" : "=l"(d) : "l"(a), "l"(b), "l"(c));
    return d;
}
__device__ __forceinline__ unsigned long long add2(unsigned long long a, unsigned long long b) {
    unsigned long long d;
    asm("add.rn.f32x2 %0, %1, %2;" : "=l"(d) : "l"(a), "l"(b));
    return d;
}
__device__ __forceinline__ unsigned long long pack2(float lo, float hi) {
    unsigned long long d;
    asm("mov.b64 %0, {%1, %2};" : "=l"(d) : "f"(lo), "f"(hi));
    return d;
}
__device__ __forceinline__ void unpack2(unsigned long long v, float& lo, float& hi) {
    asm("mov.b64 {%0, %1}, %2;" : "=f"(lo), "=f"(hi) : "l"(v));
}

// ---------------------------------------------------------------------------
// kA: per-graph A[g][j] = [imr|pgr|focus] @ W1[0:384] + b1 ; stop logits;
//     block-local cstop; block 0 also fills g_distC. (kP folded in.)
// ---------------------------------------------------------------------------
__global__ void kA(const float* __restrict__ imr, const float* __restrict__ pgr,
                   const float* __restrict__ nodes, const int* __restrict__ focus,
                   const float* __restrict__ sW1, const float* __restrict__ sb1,
                   const float* __restrict__ tW1, const float* __restrict__ tb1,
                   const float* __restrict__ sW2, const float* __restrict__ sb2,
                   const float* __restrict__ dist_table, const float* __restrict__ no_more,
                   float* __restrict__ out) {
    __shared__ float xs[8][384];
    __shared__ float sred[8][2];
    __shared__ float cst_s[64];
    int j = threadIdx.x;         // 0..127 = combined hidden col
    int g0 = blockIdx.x * 8;
    if (j < 64) {
        float s = 0.f;
#pragma unroll 4
        for (int k = 0; k < 132; k++) s += no_more[k] * sW1[(384 + k) * 64 + j];
        cst_s[j] = s;
    }
    if (blockIdx.x == 0) {
        float wj = (j < 64) ? sW1[512 * 64 + j] : tW1[512 * 64 + (j - 64)];
#pragma unroll
        for (int d = 0; d < 10; d++) g_distC[d * 128 + j] = dist_table[d] * wj;
    }
#pragma unroll
    for (int r = 0; r < 8; r++) {
        int g = g0 + r;
        xs[r][j]       = imr[g * 128 + j];
        xs[r][128 + j] = pgr[g * 128 + j];
        xs[r][256 + j] = nodes[focus[g] * 128 + j];
    }
    __syncthreads();
    bool isS = (j < 64);
    float bias = isS ? sb1[j] : tb1[j - 64];
    const float* W = isS ? (sW1 + j) : (tW1 + (j - 64));
    float acc[8];
#pragma unroll
    for (int r = 0; r < 8; r++) acc[r] = bias;
#pragma unroll 4
    for (int k = 0; k < 384; k++) {
        float w = W[k * 64];
#pragma unroll
        for (int r = 0; r < 8; r++) acc[r] = fmaf(xs[r][k], w, acc[r]);
    }
#pragma unroll
    for (int r = 0; r < 8; r++) g_A[(g0 + r) * 128 + j] = acc[r];

    float ws2 = isS ? sW2[j] : 0.f;
    float cst = isS ? cst_s[j] : 0.f;
#pragma unroll
    for (int r = 0; r < 8; r++) {
        float pv = isS ? fmaxf(acc[r] + cst, 0.f) * ws2 : 0.f;
#pragma unroll
        for (int o = 16; o >= 1; o >>= 1) pv += __shfl_xor_sync(0xffffffffu, pv, o);
        if ((j & 31) == 0 && isS) sred[r][j >> 5] = pv;
    }
    __syncthreads();
    if (j < 8) out[E_ + g0 + j] = sred[j][0] + sred[j][1] + sb2[0];
}

// ---------------------------------------------------------------------------
// kB: C[n][j] = node_reps[n] @ W1combined[384:512] + A[n2g[n]][j]
//     512 blocks x 256 threads, 128x128 tile, thread 8x8, packed f32x2.
// ---------------------------------------------------------------------------
__global__ __launch_bounds__(256) void kB(const float* __restrict__ nodes,
                                          const float* __restrict__ sW1,
                                          const float* __restrict__ tW1,
                                          const int* __restrict__ n2g) {
    __shared__ float xs[32][132];   // [k][r] transposed, padded
    __shared__ float sw[32][128];   // [k][j] combined cols
    int tid = threadIdx.x;
    int tx = tid & 15, ty = tid >> 4;
    int c0 = tx * 8, r0 = ty * 8;
    int row0 = blockIdx.x * 128;

    unsigned long long acc[4][8];
#pragma unroll
    for (int i = 0; i < 4; i++)
#pragma unroll
        for (int j = 0; j < 8; j++) acc[i][j] = 0ull;

    for (int kc = 0; kc < 128; kc += 32) {
        for (int i = tid; i < 32 * 128; i += 256) {
            int k = i >> 7, j = i & 127;
            sw[k][j] = (j < 64) ? sW1[(384 + kc + k) * 64 + j]
                                : tW1[(384 + kc + k) * 64 + (j - 64)];
        }
        for (int f = tid; f < 1024; f += 256) {
            int r = f >> 3, kq = (f & 7) << 2;
            float4 v = *(const float4*)(nodes + (size_t)(row0 + r) * 128 + kc + kq);
            xs[kq + 0][r] = v.x; xs[kq + 1][r] = v.y;
            xs[kq + 2][r] = v.z; xs[kq + 3][r] = v.w;
        }
        __syncthreads();
#pragma unroll 8
        for (int k = 0; k < 32; k++) {
            const unsigned long long* xp = (const unsigned long long*)&xs[k][r0];
            unsigned long long x0 = xp[0], x1 = xp[1], x2 = xp[2], x3 = xp[3];
            float4 wa = *(const float4*)&sw[k][c0];
            float4 wb = *(const float4*)&sw[k][c0 + 4];
            unsigned long long wd[8];
            wd[0] = pack2(wa.x, wa.x); wd[1] = pack2(wa.y, wa.y);
            wd[2] = pack2(wa.z, wa.z); wd[3] = pack2(wa.w, wa.w);
            wd[4] = pack2(wb.x, wb.x); wd[5] = pack2(wb.y, wb.y);
            wd[6] = pack2(wb.z, wb.z); wd[7] = pack2(wb.w, wb.w);
#pragma unroll
            for (int j = 0; j < 8; j++) {
                acc[0][j] = fma2(x0, wd[j], acc[0][j]);
                acc[1][j] = fma2(x1, wd[j], acc[1][j]);
                acc[2][j] = fma2(x2, wd[j], acc[2][j]);
                acc[3][j] = fma2(x3, wd[j], acc[3][j]);
            }
        }
        __syncthreads();
    }
#pragma unroll
    for (int i = 0; i < 4; i++) {
        float lo[8], hi[8];
#pragma unroll
        for (int j = 0; j < 8; j++) unpack2(acc[i][j], lo[j], hi[j]);
        int rowA = row0 + r0 + 2 * i;
        int gA = n2g[rowA], gB = n2g[rowA + 1];
        const float4* Aa = (const float4*)(g_A + (size_t)gA * 128 + c0);
        const float4* Ab = (const float4*)(g_A + (size_t)gB * 128 + c0);
        float4 a0 = Aa[0], a1 = Aa[1], b0 = Ab[0], b1 = Ab[1];
        float* o0 = g_C + (size_t)rowA * 128 + c0;
        float* o1 = o0 + 128;
        *(float4*)(o0)     = make_float4(lo[0] + a0.x, lo[1] + a0.y, lo[2] + a0.z, lo[3] + a0.w);
        *(float4*)(o0 + 4) = make_float4(lo[4] + a1.x, lo[5] + a1.y, lo[6] + a1.z, lo[7] + a1.w);
        *(float4*)(o1)     = make_float4(hi[0] + b0.x, hi[1] + b0.y, hi[2] + b0.z, hi[3] + b0.w);
        *(float4*)(o1 + 4) = make_float4(hi[4] + b1.x, hi[5] + b1.y, hi[6] + b1.z, hi[7] + b1.w);
    }
}

// ---------------------------------------------------------------------------
// kE: 2 edges per warp. Each 16-lane half owns one edge; lane owns 8 combined
//     cols (sub 0-7 scorer cols 0-63, sub 8-15 type cols 64-127).
//     Octet butterflies (3 rounds) + 1 cross-octet swap carry all 4 sums.
// ---------------------------------------------------------------------------
__global__ __launch_bounds__(256) void kE(const int* __restrict__ targets,
                   const float4* __restrict__ feats4,
                   const float* __restrict__ sW1, const float* __restrict__ tW1,
                   const float* __restrict__ sW2, const float* __restrict__ sb2,
                   const float* __restrict__ tW2, const float* __restrict__ tb2,
                   float* __restrict__ out) {
    __shared__ __align__(16) float sdc[10 * 128];
    for (int i = threadIdx.x; i < 10 * 128; i += 256) sdc[i] = g_distC[i];
    __syncthreads();

    int lane = threadIdx.x & 31;
    int sub = lane & 15;
    bool isS = (sub < 8);
    int wc = (sub & 7) * 8;                 // col base within the 64-wide W1
    int cb = wc + (isS ? 0 : 64);           // col base within combined 128
    const float* W1 = isS ? sW1 : tW1;

    // packed first-layer feature weights (rows 513..515), 8 cols per lane
    unsigned long long w513p[4], w514p[4], w515p[4];
#pragma unroll
    for (int q = 0; q < 4; q++) {
        w513p[q] = pack2(W1[513 * 64 + wc + 2 * q], W1[513 * 64 + wc + 2 * q + 1]);
        w514p[q] = pack2(W1[514 * 64 + wc + 2 * q], W1[514 * 64 + wc + 2 * q + 1]);
        w515p[q] = pack2(W1[515 * 64 + wc + 2 * q], W1[515 * 64 + wc + 2 * q + 1]);
    }
    // second-layer weights: x-slot, y-slot, z-slot (scorer octets have zeros in y/z)
    float wx[8], wy[8], wz[8];
#pragma unroll
    for (int i = 0; i < 8; i++) {
        if (isS) {
            wx[i] = sW2[wc + i]; wy[i] = 0.f; wz[i] = 0.f;
        } else {
            wx[i] = tW2[(wc + i) * 3 + 0];   // t0
            wz[i] = tW2[(wc + i) * 3 + 1];   // t1 (shipped to scorer octet)
            wy[i] = tW2[(wc + i) * 3 + 2];   // t2
        }
    }
    float sb2v = sb2[0];
    float tb0 = tb2[0], tb1v = tb2[1], tb2v = tb2[2];
    float* outT = out + (E_ + G_);

    int gw = (blockIdx.x * blockDim.x + threadIdx.x) >> 5;
    int nw = (gridDim.x * blockDim.x) >> 5;
    int eb = 2 * gw + (lane >> 4);          // this half-warp's edge
    int estep = 2 * nw;

#pragma unroll 2
    for (int e = eb; e < E_; e += estep) {
        int t = targets[e];
        float4 f = feats4[e];
        int d = (int)fminf(f.x, 9.0f);
        unsigned long long fy2 = pack2(f.y, f.y);
        unsigned long long fz2 = pack2(f.z, f.z);
        unsigned long long fw2 = pack2(f.w, f.w);

        const ulonglong2* crow = (const ulonglong2*)(g_C + (size_t)t * 128 + cb);
        ulonglong2 ca = crow[0], cbv = crow[1];
        const ulonglong2* drow = (const ulonglong2*)(sdc + d * 128 + cb);
        ulonglong2 da = drow[0], db = drow[1];

        unsigned long long a0 = add2(ca.x, da.x);
        unsigned long long a1 = add2(ca.y, da.y);
        unsigned long long a2 = add2(cbv.x, db.x);
        unsigned long long a3 = add2(cbv.y, db.y);
        a0 = fma2(fy2, w513p[0], a0); a1 = fma2(fy2, w513p[1], a1);
        a2 = fma2(fy2, w513p[2], a2); a3 = fma2(fy2, w513p[3], a3);
        a0 = fma2(fz2, w514p[0], a0); a1 = fma2(fz2, w514p[1], a1);
        a2 = fma2(fz2, w514p[2], a2); a3 = fma2(fz2, w514p[3], a3);
        a0 = fma2(fw2, w515p[0], a0); a1 = fma2(fw2, w515p[1], a1);
        a2 = fma2(fw2, w515p[2], a2); a3 = fma2(fw2, w515p[3], a3);

        float h[8];
        unpack2(a0, h[0], h[1]); unpack2(a1, h[2], h[3]);
        unpack2(a2, h[4], h[5]); unpack2(a3, h[6], h[7]);
#pragma unroll
        for (int i = 0; i < 8; i++) h[i] = fmaxf(h[i], 0.f);

        float xv = 0.f, yv = 0.f, zv = 0.f;
#pragma unroll
        for (int i = 0; i < 8; i++) {
            xv = fmaf(h[i], wx[i], xv);
            yv = fmaf(h[i], wy[i], yv);
            zv = fmaf(h[i], wz[i], zv);
        }
        // ship t1 (zv) from type octet to scorer octet's y-slot
        float y = __shfl_xor_sync(0xffffffffu, zv, 8);
        y = isS ? y : yv;
        float x = xv;
#pragma unroll
        for (int o = 1; o <= 4; o <<= 1) {
            x += __shfl_xor_sync(0xffffffffu, x, o);
            y += __shfl_xor_sync(0xffffffffu, y, o);
        }
        if (sub == 0) {                 // scorer octet lane 0
            out[e] = x + sb2v;          // scorer logit
            outT[3 * e + 1] = y + tb1v; // type logit 1
        }
        if (sub == 8) {                 // type octet lane 0
            outT[3 * e]     = x + tb0;  // type logit 0
            outT[3 * e + 2] = y + tb2v; // type logit 2
        }
    }
}

// ---------------------------------------------------------------------------
extern "C" void kernel_launch(void* const* d_in, const int* in_sizes, int n_in,
                              void* d_out, int out_size) {
    const float* imr     = (const float*)d_in[0];
    const float* pgr     = (const float*)d_in[1];
    const float* nodes   = (const float*)d_in[2];
    const int*   focus   = (const int*)d_in[3];
    const int*   n2g     = (const int*)d_in[4];
    const int*   targets = (const int*)d_in[5];
    const float* feats   = (const float*)d_in[6];
    int p = 7;
    if (p < n_in && in_sizes[p] == 1) p++;  // skip num_graphs_in_batch scalar if present
    const float* dist_table = (const float*)d_in[p++];  // [10]
    const float* no_more    = (const float*)d_in[p++];  // [132]
    const float* sW1 = (const float*)d_in[p++];         // [516,64]
    const float* sb1 = (const float*)d_in[p++];         // [64]
    const float* sW2 = (const float*)d_in[p++];         // [64]
    const float* sb2 = (const float*)d_in[p++];         // [1]
    const float* tW1 = (const float*)d_in[p++];         // [516,64]
    const float* tb1 = (const float*)d_in[p++];         // [64]
    const float* tW2 = (const float*)d_in[p++];         // [64,3]
    const float* tb2 = (const float*)d_in[p++];         // [3]
    float* out = (float*)d_out;

    kA<<<G_ / 8, 128>>>(imr, pgr, nodes, focus, sW1, sb1, tW1, tb1, sW2, sb2,
                        dist_table, no_more, out);
    kB<<<N_ / 128, 256>>>(nodes, sW1, tW1, n2g);
    kE<<<1184, 256>>>(targets, (const float4*)feats, sW1, tW1, sW2, sb2, tW2, tb2, out);
}

// round 4
// speedup vs baseline: 1.0390x; 1.0390x over previous
#include <cuda_runtime.h>

#define G_   1024
#define N_   65536
#define D_   128
#define E_   400000

// Scratch (device globals — no allocations allowed)
__device__ __align__(16) float g_A[G_ * 128];      // graph_and_focus @ W1[0:384] + b1 (64 scorer | 64 type cols)
__device__ __align__(16) float g_C[N_ * 128];      // node @ W1[384:512] + A[n2g[node]] (fused per-node table)
__device__ __align__(16) float g_distC[10 * 128];  // dist_table[d] * W1[512]
__device__ float g_cstop[64];                      // no_more_edges_rep @ scorer_W1[384:516]

// packed f32x2 helpers (full-rate FMA pipe; scalar 3-reg FFMA is half-rate)
__device__ __forceinline__ unsigned long long fma2(unsigned long long a, unsigned long long b,
                                                   unsigned long long c) {
    unsigned long long d;
    asm("fma.rn.f32x2 %0, %1, %2, %3;" : "=l"(d) : "l"(a), "l"(b), "l"(c));
    return d;
}
__device__ __forceinline__ unsigned long long add2(unsigned long long a, unsigned long long b) {
    unsigned long long d;
    asm("add.rn.f32x2 %0, %1, %2;" : "=l"(d) : "l"(a), "l"(b));
    return d;
}
__device__ __forceinline__ unsigned long long pack2(float lo, float hi) {
    unsigned long long d;
    asm("mov.b64 %0, {%1, %2};" : "=l"(d) : "f"(lo), "f"(hi));
    return d;
}
__device__ __forceinline__ void unpack2(unsigned long long v, float& lo, float& hi) {
    asm("mov.b64 {%0, %1}, %2;" : "=f"(lo), "=f"(hi) : "l"(v));
}

// ---------------------------------------------------------------------------
// kP: cstop (K-split 4 ways) + distC. 1 block x 256 threads, ~2us.
// ---------------------------------------------------------------------------
__global__ void kP(const float* __restrict__ dist_table, const float* __restrict__ no_more,
                   const float* __restrict__ sW1, const float* __restrict__ tW1) {
    __shared__ float part[4][64];
    int tid = threadIdx.x;
    int j = tid & 63, s = tid >> 6;     // 4 K-slices of 33
    float sum = 0.f;
#pragma unroll 3
    for (int k = s * 33; k < s * 33 + 33; k++)
        sum += no_more[k] * sW1[(384 + k) * 64 + j];
    part[s][j] = sum;
    __syncthreads();
    if (tid < 64)
        g_cstop[tid] = part[0][tid] + part[1][tid] + part[2][tid] + part[3][tid];
    if (tid < 128) {
        float wj = (tid < 64) ? sW1[512 * 64 + tid] : tW1[512 * 64 + (tid - 64)];
#pragma unroll
        for (int d = 0; d < 10; d++) g_distC[d * 128 + tid] = dist_table[d] * wj;
    }
}

// ---------------------------------------------------------------------------
// kA: tiled GEMM A[g][j] = [imr|pgr|focus] @ W1[0:384] + b1.
//     grid 32 x 256 threads, tile 32 rows x 128 cols, K-chunks of 32 in smem,
//     thread tile = 1 row-pair x 8 cols, packed f32x2.
// ---------------------------------------------------------------------------
__global__ __launch_bounds__(256) void kA(const float* __restrict__ imr,
                                          const float* __restrict__ pgr,
                                          const float* __restrict__ nodes,
                                          const int* __restrict__ focus,
                                          const float* __restrict__ sW1,
                                          const float* __restrict__ sb1,
                                          const float* __restrict__ tW1,
                                          const float* __restrict__ tb1) {
    __shared__ float xs[32][36];    // [k][r] transposed, padded
    __shared__ float sw[32][128];   // [k][j] combined cols
    __shared__ int foc[32];
    int tid = threadIdx.x;
    int tx = tid & 15, ty = tid >> 4;
    int c0 = tx * 8, r0 = ty * 2;   // row pair (r0, r0+1)
    int row0 = blockIdx.x * 32;
    if (tid < 32) foc[tid] = focus[row0 + tid];

    unsigned long long acc[8];
#pragma unroll
    for (int j = 0; j < 8; j++) acc[j] = 0ull;

    for (int kc = 0; kc < 384; kc += 32) {
        __syncthreads();
        // stage W chunk [32k x 128j]
        for (int i = tid; i < 32 * 128; i += 256) {
            int k = i >> 7, j = i & 127;
            sw[k][j] = (j < 64) ? sW1[(kc + k) * 64 + j]
                                : tW1[(kc + k) * 64 + (j - 64)];
        }
        // stage x chunk transposed [32k x 32r]; source depends on kc segment
        {
            int r = tid >> 3, q = (tid & 7) << 2;
            const float* src;
            if (kc < 128)      src = imr + (size_t)(row0 + r) * 128 + kc + q;
            else if (kc < 256) src = pgr + (size_t)(row0 + r) * 128 + (kc - 128) + q;
            else               src = nodes + (size_t)foc[r] * 128 + (kc - 256) + q;
            float4 v = *(const float4*)src;
            xs[q + 0][r] = v.x; xs[q + 1][r] = v.y;
            xs[q + 2][r] = v.z; xs[q + 3][r] = v.w;
        }
        __syncthreads();
#pragma unroll 8
        for (int k = 0; k < 32; k++) {
            unsigned long long x0 = *(const unsigned long long*)&xs[k][r0];
            float4 wa = *(const float4*)&sw[k][c0];
            float4 wb = *(const float4*)&sw[k][c0 + 4];
            acc[0] = fma2(x0, pack2(wa.x, wa.x), acc[0]);
            acc[1] = fma2(x0, pack2(wa.y, wa.y), acc[1]);
            acc[2] = fma2(x0, pack2(wa.z, wa.z), acc[2]);
            acc[3] = fma2(x0, pack2(wa.w, wa.w), acc[3]);
            acc[4] = fma2(x0, pack2(wb.x, wb.x), acc[4]);
            acc[5] = fma2(x0, pack2(wb.y, wb.y), acc[5]);
            acc[6] = fma2(x0, pack2(wb.z, wb.z), acc[6]);
            acc[7] = fma2(x0, pack2(wb.w, wb.w), acc[7]);
        }
    }
    // epilogue: bias + store (acc lo = row r0, hi = row r0+1)
    float lo[8], hi[8];
#pragma unroll
    for (int j = 0; j < 8; j++) unpack2(acc[j], lo[j], hi[j]);
    float* o0 = g_A + (size_t)(row0 + r0) * 128 + c0;
#pragma unroll
    for (int j = 0; j < 8; j++) {
        int c = c0 + j;
        float b = (c < 64) ? sb1[c] : tb1[c - 64];
        o0[j]       = lo[j] + b;
        o0[128 + j] = hi[j] + b;
    }
}

// ---------------------------------------------------------------------------
// kS: stop logits. One warp per graph; lane covers 2 scorer cols.
// ---------------------------------------------------------------------------
__global__ void kS(const float* __restrict__ sW2, const float* __restrict__ sb2,
                   float* __restrict__ out) {
    int lane = threadIdx.x & 31;
    int g = (blockIdx.x * blockDim.x + threadIdx.x) >> 5;   // 1024 warps exactly
    float a0 = g_A[(size_t)g * 128 + lane]      + g_cstop[lane];
    float a1 = g_A[(size_t)g * 128 + 32 + lane] + g_cstop[32 + lane];
    float v = fmaxf(a0, 0.f) * sW2[lane] + fmaxf(a1, 0.f) * sW2[32 + lane];
#pragma unroll
    for (int o = 16; o >= 1; o >>= 1) v += __shfl_xor_sync(0xffffffffu, v, o);
    if (lane == 0) out[E_ + g] = v + sb2[0];
}

// ---------------------------------------------------------------------------
// kB: C[n][j] = node_reps[n] @ W1combined[384:512] + A[n2g[n]][j]
//     512 blocks x 256 threads, 128x128 tile, thread 8x8, packed f32x2.
// ---------------------------------------------------------------------------
__global__ __launch_bounds__(256) void kB(const float* __restrict__ nodes,
                                          const float* __restrict__ sW1,
                                          const float* __restrict__ tW1,
                                          const int* __restrict__ n2g) {
    __shared__ float xs[32][132];   // [k][r] transposed, padded
    __shared__ float sw[32][128];   // [k][j] combined cols
    int tid = threadIdx.x;
    int tx = tid & 15, ty = tid >> 4;
    int c0 = tx * 8, r0 = ty * 8;
    int row0 = blockIdx.x * 128;

    unsigned long long acc[4][8];
#pragma unroll
    for (int i = 0; i < 4; i++)
#pragma unroll
        for (int j = 0; j < 8; j++) acc[i][j] = 0ull;

    for (int kc = 0; kc < 128; kc += 32) {
        for (int i = tid; i < 32 * 128; i += 256) {
            int k = i >> 7, j = i & 127;
            sw[k][j] = (j < 64) ? sW1[(384 + kc + k) * 64 + j]
                                : tW1[(384 + kc + k) * 64 + (j - 64)];
        }
        for (int f = tid; f < 1024; f += 256) {
            int r = f >> 3, kq = (f & 7) << 2;
            float4 v = *(const float4*)(nodes + (size_t)(row0 + r) * 128 + kc + kq);
            xs[kq + 0][r] = v.x; xs[kq + 1][r] = v.y;
            xs[kq + 2][r] = v.z; xs[kq + 3][r] = v.w;
        }
        __syncthreads();
#pragma unroll 8
        for (int k = 0; k < 32; k++) {
            const unsigned long long* xp = (const unsigned long long*)&xs[k][r0];
            unsigned long long x0 = xp[0], x1 = xp[1], x2 = xp[2], x3 = xp[3];
            float4 wa = *(const float4*)&sw[k][c0];
            float4 wb = *(const float4*)&sw[k][c0 + 4];
            unsigned long long wd[8];
            wd[0] = pack2(wa.x, wa.x); wd[1] = pack2(wa.y, wa.y);
            wd[2] = pack2(wa.z, wa.z); wd[3] = pack2(wa.w, wa.w);
            wd[4] = pack2(wb.x, wb.x); wd[5] = pack2(wb.y, wb.y);
            wd[6] = pack2(wb.z, wb.z); wd[7] = pack2(wb.w, wb.w);
#pragma unroll
            for (int j = 0; j < 8; j++) {
                acc[0][j] = fma2(x0, wd[j], acc[0][j]);
                acc[1][j] = fma2(x1, wd[j], acc[1][j]);
                acc[2][j] = fma2(x2, wd[j], acc[2][j]);
                acc[3][j] = fma2(x3, wd[j], acc[3][j]);
            }
        }
        __syncthreads();
    }
#pragma unroll
    for (int i = 0; i < 4; i++) {
        float lo[8], hi[8];
#pragma unroll
        for (int j = 0; j < 8; j++) unpack2(acc[i][j], lo[j], hi[j]);
        int rowA = row0 + r0 + 2 * i;
        int gA = n2g[rowA], gB = n2g[rowA + 1];
        const float4* Aa = (const float4*)(g_A + (size_t)gA * 128 + c0);
        const float4* Ab = (const float4*)(g_A + (size_t)gB * 128 + c0);
        float4 a0 = Aa[0], a1 = Aa[1], b0 = Ab[0], b1 = Ab[1];
        float* o0 = g_C + (size_t)rowA * 128 + c0;
        float* o1 = o0 + 128;
        *(float4*)(o0)     = make_float4(lo[0] + a0.x, lo[1] + a0.y, lo[2] + a0.z, lo[3] + a0.w);
        *(float4*)(o0 + 4) = make_float4(lo[4] + a1.x, lo[5] + a1.y, lo[6] + a1.z, lo[7] + a1.w);
        *(float4*)(o1)     = make_float4(hi[0] + b0.x, hi[1] + b0.y, hi[2] + b0.z, hi[3] + b0.w);
        *(float4*)(o1 + 4) = make_float4(hi[4] + b1.x, hi[5] + b1.y, hi[6] + b1.z, hi[7] + b1.w);
    }
}

// ---------------------------------------------------------------------------
// kE: 2 edges per warp. Each 16-lane half owns one edge; lane owns 8 combined
//     cols (sub 0-7 scorer cols, sub 8-15 type cols). Octet butterflies.
// ---------------------------------------------------------------------------
__global__ __launch_bounds__(256) void kE(const int* __restrict__ targets,
                   const float4* __restrict__ feats4,
                   const float* __restrict__ sW1, const float* __restrict__ tW1,
                   const float* __restrict__ sW2, const float* __restrict__ sb2,
                   const float* __restrict__ tW2, const float* __restrict__ tb2,
                   float* __restrict__ out) {
    __shared__ __align__(16) float sdc[10 * 128];
    for (int i = threadIdx.x; i < 10 * 128; i += 256) sdc[i] = g_distC[i];
    __syncthreads();

    int lane = threadIdx.x & 31;
    int sub = lane & 15;
    bool isS = (sub < 8);
    int wc = (sub & 7) * 8;                 // col base within 64-wide W1
    int cb = wc + (isS ? 0 : 64);           // col base within combined 128
    const float* W1 = isS ? sW1 : tW1;

    unsigned long long w513p[4], w514p[4], w515p[4];
#pragma unroll
    for (int q = 0; q < 4; q++) {
        w513p[q] = pack2(W1[513 * 64 + wc + 2 * q], W1[513 * 64 + wc + 2 * q + 1]);
        w514p[q] = pack2(W1[514 * 64 + wc + 2 * q], W1[514 * 64 + wc + 2 * q + 1]);
        w515p[q] = pack2(W1[515 * 64 + wc + 2 * q], W1[515 * 64 + wc + 2 * q + 1]);
    }
    float wx[8], wy[8], wz[8];
#pragma unroll
    for (int i = 0; i < 8; i++) {
        if (isS) {
            wx[i] = sW2[wc + i]; wy[i] = 0.f; wz[i] = 0.f;
        } else {
            wx[i] = tW2[(wc + i) * 3 + 0];   // t0
            wz[i] = tW2[(wc + i) * 3 + 1];   // t1 (shipped to scorer octet)
            wy[i] = tW2[(wc + i) * 3 + 2];   // t2
        }
    }
    float sb2v = sb2[0];
    float tb0 = tb2[0], tb1v = tb2[1], tb2v = tb2[2];
    float* outT = out + (E_ + G_);

    int gw = (blockIdx.x * blockDim.x + threadIdx.x) >> 5;
    int nw = (gridDim.x * blockDim.x) >> 5;
    int eb = 2 * gw + (lane >> 4);
    int estep = 2 * nw;

#pragma unroll 2
    for (int e = eb; e < E_; e += estep) {
        int t = targets[e];
        float4 f = feats4[e];
        int d = (int)fminf(f.x, 9.0f);
        unsigned long long fy2 = pack2(f.y, f.y);
        unsigned long long fz2 = pack2(f.z, f.z);
        unsigned long long fw2 = pack2(f.w, f.w);

        const ulonglong2* crow = (const ulonglong2*)(g_C + (size_t)t * 128 + cb);
        ulonglong2 ca = crow[0], cbv = crow[1];
        const ulonglong2* drow = (const ulonglong2*)(sdc + d * 128 + cb);
        ulonglong2 da = drow[0], db = drow[1];

        unsigned long long a0 = add2(ca.x, da.x);
        unsigned long long a1 = add2(ca.y, da.y);
        unsigned long long a2 = add2(cbv.x, db.x);
        unsigned long long a3 = add2(cbv.y, db.y);
        a0 = fma2(fy2, w513p[0], a0); a1 = fma2(fy2, w513p[1], a1);
        a2 = fma2(fy2, w513p[2], a2); a3 = fma2(fy2, w513p[3], a3);
        a0 = fma2(fz2, w514p[0], a0); a1 = fma2(fz2, w514p[1], a1);
        a2 = fma2(fz2, w514p[2], a2); a3 = fma2(fz2, w514p[3], a3);
        a0 = fma2(fw2, w515p[0], a0); a1 = fma2(fw2, w515p[1], a1);
        a2 = fma2(fw2, w515p[2], a2); a3 = fma2(fw2, w515p[3], a3);

        float h[8];
        unpack2(a0, h[0], h[1]); unpack2(a1, h[2], h[3]);
        unpack2(a2, h[4], h[5]); unpack2(a3, h[6], h[7]);
#pragma unroll
        for (int i = 0; i < 8; i++) h[i] = fmaxf(h[i], 0.f);

        float xv = 0.f, yv = 0.f, zv = 0.f;
#pragma unroll
        for (int i = 0; i < 8; i++) {
            xv = fmaf(h[i], wx[i], xv);
            yv = fmaf(h[i], wy[i], yv);
            zv = fmaf(h[i], wz[i], zv);
        }
        float y = __shfl_xor_sync(0xffffffffu, zv, 8);
        y = isS ? y : yv;
        float x = xv;
#pragma unroll
        for (int o = 1; o <= 4; o <<= 1) {
            x += __shfl_xor_sync(0xffffffffu, x, o);
            y += __shfl_xor_sync(0xffffffffu, y, o);
        }
        if (sub == 0) {
            out[e] = x + sb2v;
            outT[3 * e + 1] = y + tb1v;
        }
        if (sub == 8) {
            outT[3 * e]     = x + tb0;
            outT[3 * e + 2] = y + tb2v;
        }
    }
}

// ---------------------------------------------------------------------------
extern "C" void kernel_launch(void* const* d_in, const int* in_sizes, int n_in,
                              void* d_out, int out_size) {
    const float* imr     = (const float*)d_in[0];
    const float* pgr     = (const float*)d_in[1];
    const float* nodes   = (const float*)d_in[2];
    const int*   focus   = (const int*)d_in[3];
    const int*   n2g     = (const int*)d_in[4];
    const int*   targets = (const int*)d_in[5];
    const float* feats   = (const float*)d_in[6];
    int p = 7;
    if (p < n_in && in_sizes[p] == 1) p++;  // skip num_graphs_in_batch scalar if present
    const float* dist_table = (const float*)d_in[p++];  // [10]
    const float* no_more    = (const float*)d_in[p++];  // [132]
    const float* sW1 = (const float*)d_in[p++];         // [516,64]
    const float* sb1 = (const float*)d_in[p++];         // [64]
    const float* sW2 = (const float*)d_in[p++];         // [64]
    const float* sb2 = (const float*)d_in[p++];         // [1]
    const float* tW1 = (const float*)d_in[p++];         // [516,64]
    const float* tb1 = (const float*)d_in[p++];         // [64]
    const float* tW2 = (const float*)d_in[p++];         // [64,3]
    const float* tb2 = (const float*)d_in[p++];         // [3]
    float* out = (float*)d_out;

    kP<<<1, 256>>>(dist_table, no_more, sW1, tW1);
    kA<<<G_ / 32, 256>>>(imr, pgr, nodes, focus, sW1, sb1, tW1, tb1);
    kS<<<128, 256>>>(sW2, sb2, out);
    kB<<<N_ / 128, 256>>>(nodes, sW1, tW1, n2g);
    kE<<<1184, 256>>>(targets, (const float4*)feats, sW1, tW1, sW2, sb2, tW2, tb2, out);
}

// round 6
// speedup vs baseline: 1.0769x; 1.0365x over previous
#include <cuda_runtime.h>

#define G_   1024
#define N_   65536
#define D_   128
#define E_   400000

// Scratch (device globals — no allocations allowed)
__device__ __align__(16) float g_A[G_ * 128];      // graph_and_focus @ W1[0:384] + b1 (64 scorer | 64 type cols)
__device__ __align__(16) float g_C[N_ * 128];      // node @ W1[384:512] + A[n2g[node]] (fused per-node table)
__device__ float g_cstop[64];                      // no_more_edges_rep @ scorer_W1[384:516]

// packed f32x2 helpers (full-rate FMA pipe; scalar 3-reg FFMA is half-rate)
__device__ __forceinline__ unsigned long long fma2(unsigned long long a, unsigned long long b,
                                                   unsigned long long c) {
    unsigned long long d;
    asm("fma.rn.f32x2 %0, %1, %2, %3;" : "=l"(d) : "l"(a), "l"(b), "l"(c));
    return d;
}
__device__ __forceinline__ unsigned long long pack2(float lo, float hi) {
    unsigned long long d;
    asm("mov.b64 %0, {%1, %2};" : "=l"(d) : "f"(lo), "f"(hi));
    return d;
}
__device__ __forceinline__ void unpack2(unsigned long long v, float& lo, float& hi) {
    asm("mov.b64 {%0, %1}, %2;" : "=f"(lo), "=f"(hi) : "l"(v));
}

// ---------------------------------------------------------------------------
// kP: cstop (K-split 4 ways). 1 block x 256 threads.
// ---------------------------------------------------------------------------
__global__ void kP(const float* __restrict__ no_more, const float* __restrict__ sW1) {
    __shared__ float part[4][64];
    int tid = threadIdx.x;
    int j = tid & 63, s = tid >> 6;     // 4 K-slices of 33
    float sum = 0.f;
#pragma unroll 3
    for (int k = s * 33; k < s * 33 + 33; k++)
        sum += no_more[k] * sW1[(384 + k) * 64 + j];
    part[s][j] = sum;
    __syncthreads();
    if (tid < 64)
        g_cstop[tid] = part[0][tid] + part[1][tid] + part[2][tid] + part[3][tid];
}

// ---------------------------------------------------------------------------
// kA: tiled GEMM A[g][j] = [imr|pgr|focus] @ W1[0:384] + b1.
//     grid 32 x 256 threads, tile 32 rows x 128 cols, K-chunks of 32 in smem,
//     thread tile = 1 row-pair x 8 cols, packed f32x2.
// ---------------------------------------------------------------------------
__global__ __launch_bounds__(256) void kA(const float* __restrict__ imr,
                                          const float* __restrict__ pgr,
                                          const float* __restrict__ nodes,
                                          const int* __restrict__ focus,
                                          const float* __restrict__ sW1,
                                          const float* __restrict__ sb1,
                                          const float* __restrict__ tW1,
                                          const float* __restrict__ tb1) {
    __shared__ float xs[32][36];    // [k][r] transposed, padded
    __shared__ float sw[32][128];   // [k][j] combined cols
    __shared__ int foc[32];
    int tid = threadIdx.x;
    int tx = tid & 15, ty = tid >> 4;
    int c0 = tx * 8, r0 = ty * 2;   // row pair (r0, r0+1)
    int row0 = blockIdx.x * 32;
    if (tid < 32) foc[tid] = focus[row0 + tid];

    unsigned long long acc[8];
#pragma unroll
    for (int j = 0; j < 8; j++) acc[j] = 0ull;

    for (int kc = 0; kc < 384; kc += 32) {
        __syncthreads();
        for (int i = tid; i < 32 * 128; i += 256) {
            int k = i >> 7, j = i & 127;
            sw[k][j] = (j < 64) ? sW1[(kc + k) * 64 + j]
                                : tW1[(kc + k) * 64 + (j - 64)];
        }
        {
            int r = tid >> 3, q = (tid & 7) << 2;
            const float* src;
            if (kc < 128)      src = imr + (size_t)(row0 + r) * 128 + kc + q;
            else if (kc < 256) src = pgr + (size_t)(row0 + r) * 128 + (kc - 128) + q;
            else               src = nodes + (size_t)foc[r] * 128 + (kc - 256) + q;
            float4 v = *(const float4*)src;
            xs[q + 0][r] = v.x; xs[q + 1][r] = v.y;
            xs[q + 2][r] = v.z; xs[q + 3][r] = v.w;
        }
        __syncthreads();
#pragma unroll 8
        for (int k = 0; k < 32; k++) {
            unsigned long long x0 = *(const unsigned long long*)&xs[k][r0];
            float4 wa = *(const float4*)&sw[k][c0];
            float4 wb = *(const float4*)&sw[k][c0 + 4];
            acc[0] = fma2(x0, pack2(wa.x, wa.x), acc[0]);
            acc[1] = fma2(x0, pack2(wa.y, wa.y), acc[1]);
            acc[2] = fma2(x0, pack2(wa.z, wa.z), acc[2]);
            acc[3] = fma2(x0, pack2(wa.w, wa.w), acc[3]);
            acc[4] = fma2(x0, pack2(wb.x, wb.x), acc[4]);
            acc[5] = fma2(x0, pack2(wb.y, wb.y), acc[5]);
            acc[6] = fma2(x0, pack2(wb.z, wb.z), acc[6]);
            acc[7] = fma2(x0, pack2(wb.w, wb.w), acc[7]);
        }
    }
    float lo[8], hi[8];
#pragma unroll
    for (int j = 0; j < 8; j++) unpack2(acc[j], lo[j], hi[j]);
    float* o0 = g_A + (size_t)(row0 + r0) * 128 + c0;
#pragma unroll
    for (int j = 0; j < 8; j++) {
        int c = c0 + j;
        float b = (c < 64) ? sb1[c] : tb1[c - 64];
        o0[j]       = lo[j] + b;
        o0[128 + j] = hi[j] + b;
    }
}

// ---------------------------------------------------------------------------
// kS: stop logits. One warp per graph; lane covers 2 scorer cols.
// ---------------------------------------------------------------------------
__global__ void kS(const float* __restrict__ sW2, const float* __restrict__ sb2,
                   float* __restrict__ out) {
    int lane = threadIdx.x & 31;
    int g = (blockIdx.x * blockDim.x + threadIdx.x) >> 5;   // 1024 warps exactly
    float a0 = g_A[(size_t)g * 128 + lane]      + g_cstop[lane];
    float a1 = g_A[(size_t)g * 128 + 32 + lane] + g_cstop[32 + lane];
    float v = fmaxf(a0, 0.f) * sW2[lane] + fmaxf(a1, 0.f) * sW2[32 + lane];
#pragma unroll
    for (int o = 16; o >= 1; o >>= 1) v += __shfl_xor_sync(0xffffffffu, v, o);
    if (lane == 0) out[E_ + g] = v + sb2[0];
}

// ---------------------------------------------------------------------------
// kB: C[n][j] = node_reps[n] @ W1combined[384:512] + A[n2g[n]][j]
//     512 blocks x 256 threads, tile 128x128, thread tile 8 rows x 8 cols.
//     x stored DUPLICATED in smem ((x,x) pairs) so accumulators pair across
//     COLUMNS with native 64-bit w pairs -> zero pack-MOVs in the hot loop.
//     K-chunk = 16 to fit the 48KB static-smem ceiling (24.6KB total).
// ---------------------------------------------------------------------------
__global__ __launch_bounds__(256) void kB(const float* __restrict__ nodes,
                                          const float* __restrict__ sW1,
                                          const float* __restrict__ tW1,
                                          const int* __restrict__ n2g) {
    __shared__ __align__(16) float xs[16][264];   // [k][2r] duplicated pairs, padded
    __shared__ __align__(16) float sw[16][128];   // [k][j] combined cols
    int tid = threadIdx.x;
    int tx = tid & 15, ty = tid >> 4;
    int c0 = tx * 8, r0 = ty * 8;
    int row0 = blockIdx.x * 128;

    unsigned long long acc[8][4];   // [row][colpair]: cols (c0+2j, c0+2j+1)
#pragma unroll
    for (int i = 0; i < 8; i++)
#pragma unroll
        for (int j = 0; j < 4; j++) acc[i][j] = 0ull;

    for (int kc = 0; kc < 128; kc += 16) {
        // stage W chunk [16k x 128j]
        for (int i = tid; i < 16 * 128; i += 256) {
            int k = i >> 7, j = i & 127;
            sw[k][j] = (j < 64) ? sW1[(384 + kc + k) * 64 + j]
                                : tW1[(384 + kc + k) * 64 + (j - 64)];
        }
        // stage x chunk transposed+duplicated [16k x 128r pairs]
        for (int f = tid; f < 512; f += 256) {
            int r = f >> 2, kq = (f & 3) << 2;
            float4 v = *(const float4*)(nodes + (size_t)(row0 + r) * 128 + kc + kq);
            ((unsigned long long*)&xs[kq + 0][0])[r] = pack2(v.x, v.x);
            ((unsigned long long*)&xs[kq + 1][0])[r] = pack2(v.y, v.y);
            ((unsigned long long*)&xs[kq + 2][0])[r] = pack2(v.z, v.z);
            ((unsigned long long*)&xs[kq + 3][0])[r] = pack2(v.w, v.w);
        }
        __syncthreads();
#pragma unroll
        for (int k = 0; k < 16; k++) {
            const unsigned long long* xd = (const unsigned long long*)&xs[k][2 * r0];
            unsigned long long x0 = xd[0], x1 = xd[1], x2 = xd[2], x3 = xd[3];
            unsigned long long x4 = xd[4], x5 = xd[5], x6 = xd[6], x7 = xd[7];
            const unsigned long long* wp = (const unsigned long long*)&sw[k][c0];
            unsigned long long w0 = wp[0], w1 = wp[1], w2 = wp[2], w3 = wp[3];
#pragma unroll
            for (int j = 0; j < 4; j++) {
                unsigned long long w = (j == 0) ? w0 : (j == 1) ? w1 : (j == 2) ? w2 : w3;
                acc[0][j] = fma2(x0, w, acc[0][j]);
                acc[1][j] = fma2(x1, w, acc[1][j]);
                acc[2][j] = fma2(x2, w, acc[2][j]);
                acc[3][j] = fma2(x3, w, acc[3][j]);
                acc[4][j] = fma2(x4, w, acc[4][j]);
                acc[5][j] = fma2(x5, w, acc[5][j]);
                acc[6][j] = fma2(x6, w, acc[6][j]);
                acc[7][j] = fma2(x7, w, acc[7][j]);
            }
        }
        __syncthreads();
    }
    // epilogue: unpack, add A[n2g[row]] (n2g sorted -> near-sequential), store
#pragma unroll
    for (int i = 0; i < 8; i++) {
        int row = row0 + r0 + i;
        int g = n2g[row];
        const float4* Ar = (const float4*)(g_A + (size_t)g * 128 + c0);
        float4 a0 = Ar[0], a1 = Ar[1];
        float4 s0, s1;
        unpack2(acc[i][0], s0.x, s0.y); unpack2(acc[i][1], s0.z, s0.w);
        unpack2(acc[i][2], s1.x, s1.y); unpack2(acc[i][3], s1.z, s1.w);
        s0.x += a0.x; s0.y += a0.y; s0.z += a0.z; s0.w += a0.w;
        s1.x += a1.x; s1.y += a1.y; s1.z += a1.z; s1.w += a1.w;
        float* o = g_C + (size_t)row * 128 + c0;
        *(float4*)(o)     = s0;
        *(float4*)(o + 4) = s1;
    }
}

// ---------------------------------------------------------------------------
// kE: 1 edge per warp (R2 shape), lane owns 4 combined cols
//     (lanes 0-15 scorer, 16-31 type). Dist handled as scalar fma against
//     w512 regs (no 512B distC row load). Software-pipelined prefetch of
//     next edge's (t, f, C-row) to hide the t->C L2 chain.
// ---------------------------------------------------------------------------
__global__ __launch_bounds__(256) void kE(const int* __restrict__ targets,
                   const float4* __restrict__ feats4,
                   const float* __restrict__ sW1, const float* __restrict__ tW1,
                   const float* __restrict__ sW2, const float* __restrict__ sb2,
                   const float* __restrict__ tW2, const float* __restrict__ tb2,
                   const float* __restrict__ dist_table,
                   float* __restrict__ out) {
    __shared__ float sdt[10];
    if (threadIdx.x < 10) sdt[threadIdx.x] = dist_table[threadIdx.x];
    __syncthreads();

    int lane = threadIdx.x & 31;
    bool isS = (lane < 16);
    int cbase = (lane & 15) * 4;
    const float* W1 = isS ? sW1 : tW1;
    float4 w512 = *(const float4*)(W1 + 512 * 64 + cbase);
    float4 w513 = *(const float4*)(W1 + 513 * 64 + cbase);
    float4 w514 = *(const float4*)(W1 + 514 * 64 + cbase);
    float4 w515 = *(const float4*)(W1 + 515 * 64 + cbase);
    // unified second-layer coefficients: u0 -> p-path, u1/u2 -> q-paths
    float4 u0, u1, u2;
    if (isS) {
        u0 = *(const float4*)(sW2 + cbase);
        u1 = make_float4(0.f, 0.f, 0.f, 0.f);
        u2 = u1;
    } else {
        u0.x = tW2[(cbase + 0) * 3]; u0.y = tW2[(cbase + 1) * 3];
        u0.z = tW2[(cbase + 2) * 3]; u0.w = tW2[(cbase + 3) * 3];
        u1.x = tW2[(cbase + 0) * 3 + 1]; u1.y = tW2[(cbase + 1) * 3 + 1];
        u1.z = tW2[(cbase + 2) * 3 + 1]; u1.w = tW2[(cbase + 3) * 3 + 1];
        u2.x = tW2[(cbase + 0) * 3 + 2]; u2.y = tW2[(cbase + 1) * 3 + 2];
        u2.z = tW2[(cbase + 2) * 3 + 2]; u2.w = tW2[(cbase + 3) * 3 + 2];
    }
    float sb2v = sb2[0];
    float tb0 = tb2[0], tb1v = tb2[1], tb2v = tb2[2];
    const float4* C4 = (const float4*)g_C;
    float* outT = out + (E_ + G_);

    int gw = (blockIdx.x * blockDim.x + threadIdx.x) >> 5;
    int nw = (gridDim.x * blockDim.x) >> 5;

    int e = gw;
    float4 f, c;
    if (e < E_) {
        int t = targets[e];
        f = feats4[e];
        c = C4[(size_t)t * 32 + lane];
    }
    while (e < E_) {
        // prefetch next edge (independent chain; hides L2 latency)
        int e2 = e + nw;
        float4 f2, c2;
        if (e2 < E_) {
            int t2 = targets[e2];
            f2 = feats4[e2];
            c2 = C4[(size_t)t2 * 32 + lane];
        }
        // compute current edge
        float dv = sdt[(int)fminf(f.x, 9.0f)];
        float hx = fmaxf(fmaf(dv, w512.x, fmaf(f.y, w513.x, fmaf(f.z, w514.x, fmaf(f.w, w515.x, c.x)))), 0.f);
        float hy = fmaxf(fmaf(dv, w512.y, fmaf(f.y, w513.y, fmaf(f.z, w514.y, fmaf(f.w, w515.y, c.y)))), 0.f);
        float hz = fmaxf(fmaf(dv, w512.z, fmaf(f.y, w513.z, fmaf(f.z, w514.z, fmaf(f.w, w515.z, c.z)))), 0.f);
        float hw = fmaxf(fmaf(dv, w512.w, fmaf(f.y, w513.w, fmaf(f.z, w514.w, fmaf(f.w, w515.w, c.w)))), 0.f);
        float v0 = fmaf(hx, u0.x, fmaf(hy, u0.y, fmaf(hz, u0.z, hw * u0.w)));
        float v1 = fmaf(hx, u1.x, fmaf(hy, u1.y, fmaf(hz, u1.z, hw * u1.w)));
        float v2 = fmaf(hx, u2.x, fmaf(hy, u2.y, fmaf(hz, u2.z, hw * u2.w)));
        // dual 16-lane butterfly: p = {scorer v0 | type t1}, q = {type v0 | type t2}
        float p = isS ? v0 : v1;
        float q = __shfl_xor_sync(0xffffffffu, v0, 16);
        q = isS ? q : v2;
#pragma unroll
        for (int o = 1; o <= 8; o <<= 1) {
            p += __shfl_xor_sync(0xffffffffu, p, o);
            q += __shfl_xor_sync(0xffffffffu, q, o);
        }
        if (lane == 0) {
            out[e] = p + sb2v;          // scorer logit
            outT[3 * e] = q + tb0;      // type logit 0
        }
        if (lane == 16) {
            outT[3 * e + 1] = p + tb1v; // type logit 1
            outT[3 * e + 2] = q + tb2v; // type logit 2
        }
        e = e2; f = f2; c = c2;
    }
}

// ---------------------------------------------------------------------------
extern "C" void kernel_launch(void* const* d_in, const int* in_sizes, int n_in,
                              void* d_out, int out_size) {
    const float* imr     = (const float*)d_in[0];
    const float* pgr     = (const float*)d_in[1];
    const float* nodes   = (const float*)d_in[2];
    const int*   focus   = (const int*)d_in[3];
    const int*   n2g     = (const int*)d_in[4];
    const int*   targets = (const int*)d_in[5];
    const float* feats   = (const float*)d_in[6];
    int p = 7;
    if (p < n_in && in_sizes[p] == 1) p++;  // skip num_graphs_in_batch scalar if present
    const float* dist_table = (const float*)d_in[p++];  // [10]
    const float* no_more    = (const float*)d_in[p++];  // [132]
    const float* sW1 = (const float*)d_in[p++];         // [516,64]
    const float* sb1 = (const float*)d_in[p++];         // [64]
    const float* sW2 = (const float*)d_in[p++];         // [64]
    const float* sb2 = (const float*)d_in[p++];         // [1]
    const float* tW1 = (const float*)d_in[p++];         // [516,64]
    const float* tb1 = (const float*)d_in[p++];         // [64]
    const float* tW2 = (const float*)d_in[p++];         // [64,3]
    const float* tb2 = (const float*)d_in[p++];         // [3]
    float* out = (float*)d_out;

    kP<<<1, 256>>>(no_more, sW1);
    kA<<<G_ / 32, 256>>>(imr, pgr, nodes, focus, sW1, sb1, tW1, tb1);
    kS<<<128, 256>>>(sW2, sb2, out);
    kB<<<N_ / 128, 256>>>(nodes, sW1, tW1, n2g);
    kE<<<1184, 256>>>(targets, (const float4*)feats, sW1, tW1, sW2, sb2, tW2, tb2,
                      dist_table, out);
}

// round 8
// speedup vs baseline: 1.2621x; 1.1719x over previous
#include <cuda_runtime.h>

#define G_   1024
#define N_   65536
#define D_   128
#define E_   400000

// Scratch (device globals — no allocations allowed)
__device__ __align__(16) float g_A[G_ * 128];      // graph_and_focus @ W1[0:384] + b1 (64 scorer | 64 type cols)
__device__ __align__(16) float g_C[N_ * 128];      // node @ W1[384:512] + A[n2g[node]] (fused per-node table)
__device__ float g_cstop[64];                      // no_more_edges_rep @ scorer_W1[384:516]

// packed f32x2 helpers (full-rate FMA pipe; scalar 3-reg FFMA is half-rate)
__device__ __forceinline__ unsigned long long fma2(unsigned long long a, unsigned long long b,
                                                   unsigned long long c) {
    unsigned long long d;
    asm("fma.rn.f32x2 %0, %1, %2, %3;" : "=l"(d) : "l"(a), "l"(b), "l"(c));
    return d;
}
__device__ __forceinline__ unsigned long long pack2(float lo, float hi) {
    unsigned long long d;
    asm("mov.b64 %0, {%1, %2};" : "=l"(d) : "f"(lo), "f"(hi));
    return d;
}
__device__ __forceinline__ void unpack2(unsigned long long v, float& lo, float& hi) {
    asm("mov.b64 {%0, %1}, %2;" : "=f"(lo), "=f"(hi) : "l"(v));
}

// ---------------------------------------------------------------------------
// kP: cstop (K-split 4 ways). 1 block x 256 threads.
// ---------------------------------------------------------------------------
__global__ void kP(const float* __restrict__ no_more, const float* __restrict__ sW1) {
    __shared__ float part[4][64];
    int tid = threadIdx.x;
    int j = tid & 63, s = tid >> 6;
    float sum = 0.f;
#pragma unroll 3
    for (int k = s * 33; k < s * 33 + 33; k++)
        sum += no_more[k] * sW1[(384 + k) * 64 + j];
    part[s][j] = sum;
    __syncthreads();
    if (tid < 64)
        g_cstop[tid] = part[0][tid] + part[1][tid] + part[2][tid] + part[3][tid];
}

// ---------------------------------------------------------------------------
// kA: per-graph A[g][j] = [imr|pgr|focus] @ W1[0:384] + b1 ; stop logits inline.
//     (R2 shape, measured ~20us with kP: 128 blocks x 128 threads, 8 graphs/blk)
// ---------------------------------------------------------------------------
__global__ void kA(const float* __restrict__ imr, const float* __restrict__ pgr,
                   const float* __restrict__ nodes, const int* __restrict__ focus,
                   const float* __restrict__ sW1, const float* __restrict__ sb1,
                   const float* __restrict__ tW1, const float* __restrict__ tb1,
                   const float* __restrict__ sW2, const float* __restrict__ sb2,
                   float* __restrict__ out) {
    __shared__ float xs[8][384];
    __shared__ float sred[8][2];
    int j = threadIdx.x;
    int g0 = blockIdx.x * 8;
#pragma unroll
    for (int r = 0; r < 8; r++) {
        int g = g0 + r;
        xs[r][j]       = imr[g * 128 + j];
        xs[r][128 + j] = pgr[g * 128 + j];
        xs[r][256 + j] = nodes[(size_t)focus[g] * 128 + j];
    }
    __syncthreads();
    bool isS = (j < 64);
    float bias = isS ? sb1[j] : tb1[j - 64];
    const float* W = isS ? (sW1 + j) : (tW1 + (j - 64));
    float acc[8];
#pragma unroll
    for (int r = 0; r < 8; r++) acc[r] = bias;
#pragma unroll 4
    for (int k = 0; k < 384; k++) {
        float w = W[k * 64];
#pragma unroll
        for (int r = 0; r < 8; r++) acc[r] = fmaf(xs[r][k], w, acc[r]);
    }
#pragma unroll
    for (int r = 0; r < 8; r++) g_A[(size_t)(g0 + r) * 128 + j] = acc[r];

    float ws2 = isS ? sW2[j] : 0.f;
    float cst = isS ? g_cstop[j] : 0.f;
#pragma unroll
    for (int r = 0; r < 8; r++) {
        float pv = isS ? fmaxf(acc[r] + cst, 0.f) * ws2 : 0.f;
#pragma unroll
        for (int o = 16; o >= 1; o >>= 1) pv += __shfl_xor_sync(0xffffffffu, pv, o);
        if ((j & 31) == 0 && isS) sred[r][j >> 5] = pv;
    }
    __syncthreads();
    if (j < 8) out[E_ + g0 + j] = sred[j][0] + sred[j][1] + sb2[0];
}

// ---------------------------------------------------------------------------
// kB: C[n][j] = node_reps[n] @ W1combined[384:512] + A[n2g[n]][j]
//     (R2/R4 shape, measured 84us) 512 blocks x 256 threads, tile 128x128,
//     thread 8x8, packed f32x2 with row-pair accumulators.
// ---------------------------------------------------------------------------
__global__ __launch_bounds__(256) void kB(const float* __restrict__ nodes,
                                          const float* __restrict__ sW1,
                                          const float* __restrict__ tW1,
                                          const int* __restrict__ n2g) {
    __shared__ float xs[32][132];   // [k][r] transposed, padded
    __shared__ float sw[32][128];   // [k][j] combined cols
    int tid = threadIdx.x;
    int tx = tid & 15, ty = tid >> 4;
    int c0 = tx * 8, r0 = ty * 8;
    int row0 = blockIdx.x * 128;

    unsigned long long acc[4][8];   // [row-pair][col]: rows (r0+2i, r0+2i+1)
#pragma unroll
    for (int i = 0; i < 4; i++)
#pragma unroll
        for (int j = 0; j < 8; j++) acc[i][j] = 0ull;

    for (int kc = 0; kc < 128; kc += 32) {
        for (int i = tid; i < 32 * 128; i += 256) {
            int k = i >> 7, j = i & 127;
            sw[k][j] = (j < 64) ? sW1[(384 + kc + k) * 64 + j]
                                : tW1[(384 + kc + k) * 64 + (j - 64)];
        }
        for (int f = tid; f < 1024; f += 256) {
            int r = f >> 3, kq = (f & 7) << 2;
            float4 v = *(const float4*)(nodes + (size_t)(row0 + r) * 128 + kc + kq);
            xs[kq + 0][r] = v.x; xs[kq + 1][r] = v.y;
            xs[kq + 2][r] = v.z; xs[kq + 3][r] = v.w;
        }
        __syncthreads();
#pragma unroll 8
        for (int k = 0; k < 32; k++) {
            const unsigned long long* xp = (const unsigned long long*)&xs[k][r0];
            unsigned long long x0 = xp[0], x1 = xp[1], x2 = xp[2], x3 = xp[3];
            float4 wa = *(const float4*)&sw[k][c0];
            float4 wb = *(const float4*)&sw[k][c0 + 4];
            unsigned long long wd[8];
            wd[0] = pack2(wa.x, wa.x); wd[1] = pack2(wa.y, wa.y);
            wd[2] = pack2(wa.z, wa.z); wd[3] = pack2(wa.w, wa.w);
            wd[4] = pack2(wb.x, wb.x); wd[5] = pack2(wb.y, wb.y);
            wd[6] = pack2(wb.z, wb.z); wd[7] = pack2(wb.w, wb.w);
#pragma unroll
            for (int j = 0; j < 8; j++) {
                acc[0][j] = fma2(x0, wd[j], acc[0][j]);
                acc[1][j] = fma2(x1, wd[j], acc[1][j]);
                acc[2][j] = fma2(x2, wd[j], acc[2][j]);
                acc[3][j] = fma2(x3, wd[j], acc[3][j]);
            }
        }
        __syncthreads();
    }
#pragma unroll
    for (int i = 0; i < 4; i++) {
        float lo[8], hi[8];
#pragma unroll
        for (int j = 0; j < 8; j++) unpack2(acc[i][j], lo[j], hi[j]);
        int rowA = row0 + r0 + 2 * i;
        int gA = n2g[rowA], gB = n2g[rowA + 1];
        const float4* Aa = (const float4*)(g_A + (size_t)gA * 128 + c0);
        const float4* Ab = (const float4*)(g_A + (size_t)gB * 128 + c0);
        float4 a0 = Aa[0], a1 = Aa[1], b0 = Ab[0], b1 = Ab[1];
        float* o0 = g_C + (size_t)rowA * 128 + c0;
        float* o1 = o0 + 128;
        *(float4*)(o0)     = make_float4(lo[0] + a0.x, lo[1] + a0.y, lo[2] + a0.z, lo[3] + a0.w);
        *(float4*)(o0 + 4) = make_float4(lo[4] + a1.x, lo[5] + a1.y, lo[6] + a1.z, lo[7] + a1.w);
        *(float4*)(o1)     = make_float4(hi[0] + b0.x, hi[1] + b0.y, hi[2] + b0.z, hi[3] + b0.w);
        *(float4*)(o1 + 4) = make_float4(hi[4] + b1.x, hi[5] + b1.y, hi[6] + b1.z, hi[7] + b1.w);
    }
}

// ---------------------------------------------------------------------------
// kE: 1 edge per warp, lane owns 4 combined cols (lanes 0-15 scorer, 16-31
//     type). Scalar dist fma vs w512 regs; 1-deep prefetch of targets->C chain.
//     (R6 shape, implied ~41us)
// ---------------------------------------------------------------------------
__global__ __launch_bounds__(256) void kE(const int* __restrict__ targets,
                   const float4* __restrict__ feats4,
                   const float* __restrict__ sW1, const float* __restrict__ tW1,
                   const float* __restrict__ sW2, const float* __restrict__ sb2,
                   const float* __restrict__ tW2, const float* __restrict__ tb2,
                   const float* __restrict__ dist_table,
                   float* __restrict__ out) {
    __shared__ float sdt[10];
    if (threadIdx.x < 10) sdt[threadIdx.x] = dist_table[threadIdx.x];
    __syncthreads();

    int lane = threadIdx.x & 31;
    bool isS = (lane < 16);
    int cbase = (lane & 15) * 4;
    const float* W1 = isS ? sW1 : tW1;
    float4 w512 = *(const float4*)(W1 + 512 * 64 + cbase);
    float4 w513 = *(const float4*)(W1 + 513 * 64 + cbase);
    float4 w514 = *(const float4*)(W1 + 514 * 64 + cbase);
    float4 w515 = *(const float4*)(W1 + 515 * 64 + cbase);
    float4 u0, u1, u2;
    if (isS) {
        u0 = *(const float4*)(sW2 + cbase);
        u1 = make_float4(0.f, 0.f, 0.f, 0.f);
        u2 = u1;
    } else {
        u0.x = tW2[(cbase + 0) * 3]; u0.y = tW2[(cbase + 1) * 3];
        u0.z = tW2[(cbase + 2) * 3]; u0.w = tW2[(cbase + 3) * 3];
        u1.x = tW2[(cbase + 0) * 3 + 1]; u1.y = tW2[(cbase + 1) * 3 + 1];
        u1.z = tW2[(cbase + 2) * 3 + 1]; u1.w = tW2[(cbase + 3) * 3 + 1];
        u2.x = tW2[(cbase + 0) * 3 + 2]; u2.y = tW2[(cbase + 1) * 3 + 2];
        u2.z = tW2[(cbase + 2) * 3 + 2]; u2.w = tW2[(cbase + 3) * 3 + 2];
    }
    float sb2v = sb2[0];
    float tb0 = tb2[0], tb1v = tb2[1], tb2v = tb2[2];
    const float4* C4 = (const float4*)g_C;
    float* outT = out + (E_ + G_);

    int gw = (blockIdx.x * blockDim.x + threadIdx.x) >> 5;
    int nw = (gridDim.x * blockDim.x) >> 5;

    int e = gw;
    float4 f, c;
    if (e < E_) {
        int t = targets[e];
        f = feats4[e];
        c = C4[(size_t)t * 32 + lane];
    }
    while (e < E_) {
        int e2 = e + nw;
        float4 f2, c2;
        if (e2 < E_) {
            int t2 = targets[e2];
            f2 = feats4[e2];
            c2 = C4[(size_t)t2 * 32 + lane];
        }
        float dv = sdt[(int)fminf(f.x, 9.0f)];
        float hx = fmaxf(fmaf(dv, w512.x, fmaf(f.y, w513.x, fmaf(f.z, w514.x, fmaf(f.w, w515.x, c.x)))), 0.f);
        float hy = fmaxf(fmaf(dv, w512.y, fmaf(f.y, w513.y, fmaf(f.z, w514.y, fmaf(f.w, w515.y, c.y)))), 0.f);
        float hz = fmaxf(fmaf(dv, w512.z, fmaf(f.y, w513.z, fmaf(f.z, w514.z, fmaf(f.w, w515.z, c.z)))), 0.f);
        float hw = fmaxf(fmaf(dv, w512.w, fmaf(f.y, w513.w, fmaf(f.z, w514.w, fmaf(f.w, w515.w, c.w)))), 0.f);
        float v0 = fmaf(hx, u0.x, fmaf(hy, u0.y, fmaf(hz, u0.z, hw * u0.w)));
        float v1 = fmaf(hx, u1.x, fmaf(hy, u1.y, fmaf(hz, u1.z, hw * u1.w)));
        float v2 = fmaf(hx, u2.x, fmaf(hy, u2.y, fmaf(hz, u2.z, hw * u2.w)));
        float p = isS ? v0 : v1;
        float q = __shfl_xor_sync(0xffffffffu, v0, 16);
        q = isS ? q : v2;
#pragma unroll
        for (int o = 1; o <= 8; o <<= 1) {
            p += __shfl_xor_sync(0xffffffffu, p, o);
            q += __shfl_xor_sync(0xffffffffu, q, o);
        }
        if (lane == 0) {
            out[e] = p + sb2v;          // scorer logit
            outT[3 * e] = q + tb0;      // type logit 0
        }
        if (lane == 16) {
            outT[3 * e + 1] = p + tb1v; // type logit 1
            outT[3 * e + 2] = q + tb2v; // type logit 2
        }
        e = e2; f = f2; c = c2;
    }
}

// ---------------------------------------------------------------------------
extern "C" void kernel_launch(void* const* d_in, const int* in_sizes, int n_in,
                              void* d_out, int out_size) {
    const float* imr     = (const float*)d_in[0];
    const float* pgr     = (const float*)d_in[1];
    const float* nodes   = (const float*)d_in[2];
    const int*   focus   = (const int*)d_in[3];
    const int*   n2g     = (const int*)d_in[4];
    const int*   targets = (const int*)d_in[5];
    const float* feats   = (const float*)d_in[6];
    int p = 7;
    if (p < n_in && in_sizes[p] == 1) p++;  // skip num_graphs_in_batch scalar if present
    const float* dist_table = (const float*)d_in[p++];  // [10]
    const float* no_more    = (const float*)d_in[p++];  // [132]
    const float* sW1 = (const float*)d_in[p++];         // [516,64]
    const float* sb1 = (const float*)d_in[p++];         // [64]
    const float* sW2 = (const float*)d_in[p++];         // [64]
    const float* sb2 = (const float*)d_in[p++];         // [1]
    const float* tW1 = (const float*)d_in[p++];         // [516,64]
    const float* tb1 = (const float*)d_in[p++];         // [64]
    const float* tW2 = (const float*)d_in[p++];         // [64,3]
    const float* tb2 = (const float*)d_in[p++];         // [3]
    float* out = (float*)d_out;

    kP<<<1, 256>>>(no_more, sW1);
    kA<<<G_ / 8, 128>>>(imr, pgr, nodes, focus, sW1, sb1, tW1, tb1, sW2, sb2, out);
    kB<<<N_ / 128, 256>>>(nodes, sW1, tW1, n2g);
    kE<<<1184, 256>>>(targets, (const float4*)feats, sW1, tW1, sW2, sb2, tW2, tb2,
                      dist_table, out);
}

// round 9
// speedup vs baseline: 1.3303x; 1.0540x over previous
#include <cuda_runtime.h>

#define G_   1024
#define N_   65536
#define D_   128
#define E_   400000

// Scratch (device globals — no allocations allowed)
__device__ __align__(16) float g_A[G_ * 128];      // graph_and_focus @ W1[0:384] + b1 (64 scorer | 64 type cols)
__device__ __align__(16) float g_C[N_ * 128];      // node @ W1[384:512] + A[n2g[node]] (fused per-node table)
__device__ float g_cstop[64];                      // no_more_edges_rep @ scorer_W1[384:516]

// packed f32x2 helpers (full-rate FMA pipe; scalar 3-reg FFMA is half-rate)
__device__ __forceinline__ unsigned long long fma2(unsigned long long a, unsigned long long b,
                                                   unsigned long long c) {
    unsigned long long d;
    asm("fma.rn.f32x2 %0, %1, %2, %3;" : "=l"(d) : "l"(a), "l"(b), "l"(c));
    return d;
}
__device__ __forceinline__ unsigned long long pack2(float lo, float hi) {
    unsigned long long d;
    asm("mov.b64 %0, {%1, %2};" : "=l"(d) : "f"(lo), "f"(hi));
    return d;
}
__device__ __forceinline__ void unpack2(unsigned long long v, float& lo, float& hi) {
    asm("mov.b64 {%0, %1}, %2;" : "=f"(lo), "=f"(hi) : "l"(v));
}

// ---------------------------------------------------------------------------
// kP: cstop (K-split 4 ways). 1 block x 256 threads.
// ---------------------------------------------------------------------------
__global__ void kP(const float* __restrict__ no_more, const float* __restrict__ sW1) {
    __shared__ float part[4][64];
    int tid = threadIdx.x;
    int j = tid & 63, s = tid >> 6;
    float sum = 0.f;
#pragma unroll 3
    for (int k = s * 33; k < s * 33 + 33; k++)
        sum += no_more[k] * sW1[(384 + k) * 64 + j];
    part[s][j] = sum;
    __syncthreads();
    if (tid < 64)
        g_cstop[tid] = part[0][tid] + part[1][tid] + part[2][tid] + part[3][tid];
}

// ---------------------------------------------------------------------------
// kA: per-graph A[g][j] = [imr|pgr|focus] @ W1[0:384] + b1 ; stop logits inline.
//     (measured-good R2 shape: 128 blocks x 128 threads, 8 graphs/block)
// ---------------------------------------------------------------------------
__global__ void kA(const float* __restrict__ imr, const float* __restrict__ pgr,
                   const float* __restrict__ nodes, const int* __restrict__ focus,
                   const float* __restrict__ sW1, const float* __restrict__ sb1,
                   const float* __restrict__ tW1, const float* __restrict__ tb1,
                   const float* __restrict__ sW2, const float* __restrict__ sb2,
                   float* __restrict__ out) {
    __shared__ float xs[8][384];
    __shared__ float sred[8][2];
    int j = threadIdx.x;
    int g0 = blockIdx.x * 8;
#pragma unroll
    for (int r = 0; r < 8; r++) {
        int g = g0 + r;
        xs[r][j]       = imr[g * 128 + j];
        xs[r][128 + j] = pgr[g * 128 + j];
        xs[r][256 + j] = nodes[(size_t)focus[g] * 128 + j];
    }
    __syncthreads();
    bool isS = (j < 64);
    float bias = isS ? sb1[j] : tb1[j - 64];
    const float* W = isS ? (sW1 + j) : (tW1 + (j - 64));
    float acc[8];
#pragma unroll
    for (int r = 0; r < 8; r++) acc[r] = bias;
#pragma unroll 4
    for (int k = 0; k < 384; k++) {
        float w = W[k * 64];
#pragma unroll
        for (int r = 0; r < 8; r++) acc[r] = fmaf(xs[r][k], w, acc[r]);
    }
#pragma unroll
    for (int r = 0; r < 8; r++) g_A[(size_t)(g0 + r) * 128 + j] = acc[r];

    float ws2 = isS ? sW2[j] : 0.f;
    float cst = isS ? g_cstop[j] : 0.f;
#pragma unroll
    for (int r = 0; r < 8; r++) {
        float pv = isS ? fmaxf(acc[r] + cst, 0.f) * ws2 : 0.f;
#pragma unroll
        for (int o = 16; o >= 1; o >>= 1) pv += __shfl_xor_sync(0xffffffffu, pv, o);
        if ((j & 31) == 0 && isS) sred[r][j >> 5] = pv;
    }
    __syncthreads();
    if (j < 8) out[E_ + g0 + j] = sred[j][0] + sred[j][1] + sb2[0];
}

// ---------------------------------------------------------------------------
// kB: C[n][j] = node_reps[n] @ W1combined[384:512] + A[n2g[n]][j]
//     v2: 512 blocks x 512 threads, tile 128x128, thread tile 8 rows x 4 cols.
//     Row-pair accumulators (x native ULL pairs from smem, only 4 w-packs/k).
//     __launch_bounds__(512,2) -> <=64 regs -> 2 CTAs/SM = 50% occupancy.
// ---------------------------------------------------------------------------
__global__ __launch_bounds__(512, 2) void kB(const float* __restrict__ nodes,
                                             const float* __restrict__ sW1,
                                             const float* __restrict__ tW1,
                                             const int* __restrict__ n2g) {
    __shared__ float xs[32][132];   // [k][r] transposed, padded
    __shared__ float sw[32][128];   // [k][j] combined cols
    int tid = threadIdx.x;
    int tx = tid & 31, ty = tid >> 5;   // tx: col group (4 cols), ty: row group (8 rows)
    int c0 = tx * 4, r0 = ty * 8;
    int row0 = blockIdx.x * 128;

    unsigned long long acc[4][4];   // [row-pair][col]: rows (r0+2i, r0+2i+1), col c0+j
#pragma unroll
    for (int i = 0; i < 4; i++)
#pragma unroll
        for (int j = 0; j < 4; j++) acc[i][j] = 0ull;

    for (int kc = 0; kc < 128; kc += 32) {
        // stage W chunk [32k x 128j] (4096 floats, 8 per thread)
        for (int i = tid; i < 32 * 128; i += 512) {
            int k = i >> 7, j = i & 127;
            sw[k][j] = (j < 64) ? sW1[(384 + kc + k) * 64 + j]
                                : tW1[(384 + kc + k) * 64 + (j - 64)];
        }
        // stage x chunk transposed [32k x 128r] (1024 float4, 2 per thread)
        for (int f = tid; f < 1024; f += 512) {
            int r = f >> 3, kq = (f & 7) << 2;
            float4 v = *(const float4*)(nodes + (size_t)(row0 + r) * 128 + kc + kq);
            xs[kq + 0][r] = v.x; xs[kq + 1][r] = v.y;
            xs[kq + 2][r] = v.z; xs[kq + 3][r] = v.w;
        }
        __syncthreads();
#pragma unroll 8
        for (int k = 0; k < 32; k++) {
            const unsigned long long* xp = (const unsigned long long*)&xs[k][r0];
            unsigned long long x0 = xp[0], x1 = xp[1], x2 = xp[2], x3 = xp[3];
            float4 w = *(const float4*)&sw[k][c0];
            unsigned long long w0 = pack2(w.x, w.x), w1 = pack2(w.y, w.y);
            unsigned long long w2 = pack2(w.z, w.z), w3 = pack2(w.w, w.w);
            acc[0][0] = fma2(x0, w0, acc[0][0]); acc[0][1] = fma2(x0, w1, acc[0][1]);
            acc[0][2] = fma2(x0, w2, acc[0][2]); acc[0][3] = fma2(x0, w3, acc[0][3]);
            acc[1][0] = fma2(x1, w0, acc[1][0]); acc[1][1] = fma2(x1, w1, acc[1][1]);
            acc[1][2] = fma2(x1, w2, acc[1][2]); acc[1][3] = fma2(x1, w3, acc[1][3]);
            acc[2][0] = fma2(x2, w0, acc[2][0]); acc[2][1] = fma2(x2, w1, acc[2][1]);
            acc[2][2] = fma2(x2, w2, acc[2][2]); acc[2][3] = fma2(x2, w3, acc[2][3]);
            acc[3][0] = fma2(x3, w0, acc[3][0]); acc[3][1] = fma2(x3, w1, acc[3][1]);
            acc[3][2] = fma2(x3, w2, acc[3][2]); acc[3][3] = fma2(x3, w3, acc[3][3]);
        }
        __syncthreads();
    }
    // epilogue: unpack, add A[n2g[row]] (n2g sorted -> near-sequential), store
#pragma unroll
    for (int i = 0; i < 4; i++) {
        float lo[4], hi[4];
#pragma unroll
        for (int j = 0; j < 4; j++) unpack2(acc[i][j], lo[j], hi[j]);
        int rowA = row0 + r0 + 2 * i;
        int gA = n2g[rowA], gB = n2g[rowA + 1];
        float4 a0 = *(const float4*)(g_A + (size_t)gA * 128 + c0);
        float4 b0 = *(const float4*)(g_A + (size_t)gB * 128 + c0);
        *(float4*)(g_C + (size_t)rowA * 128 + c0) =
            make_float4(lo[0] + a0.x, lo[1] + a0.y, lo[2] + a0.z, lo[3] + a0.w);
        *(float4*)(g_C + (size_t)(rowA + 1) * 128 + c0) =
            make_float4(hi[0] + b0.x, hi[1] + b0.y, hi[2] + b0.z, hi[3] + b0.w);
    }
}

// ---------------------------------------------------------------------------
// kE: 1 edge per warp, lane owns 4 combined cols (lanes 0-15 scorer, 16-31
//     type). Scalar dist fma vs w512 regs; 1-deep prefetch of targets->C chain.
//     (measured 74.4us in R8)
// ---------------------------------------------------------------------------
__global__ __launch_bounds__(256) void kE(const int* __restrict__ targets,
                   const float4* __restrict__ feats4,
                   const float* __restrict__ sW1, const float* __restrict__ tW1,
                   const float* __restrict__ sW2, const float* __restrict__ sb2,
                   const float* __restrict__ tW2, const float* __restrict__ tb2,
                   const float* __restrict__ dist_table,
                   float* __restrict__ out) {
    __shared__ float sdt[10];
    if (threadIdx.x < 10) sdt[threadIdx.x] = dist_table[threadIdx.x];
    __syncthreads();

    int lane = threadIdx.x & 31;
    bool isS = (lane < 16);
    int cbase = (lane & 15) * 4;
    const float* W1 = isS ? sW1 : tW1;
    float4 w512 = *(const float4*)(W1 + 512 * 64 + cbase);
    float4 w513 = *(const float4*)(W1 + 513 * 64 + cbase);
    float4 w514 = *(const float4*)(W1 + 514 * 64 + cbase);
    float4 w515 = *(const float4*)(W1 + 515 * 64 + cbase);
    float4 u0, u1, u2;
    if (isS) {
        u0 = *(const float4*)(sW2 + cbase);
        u1 = make_float4(0.f, 0.f, 0.f, 0.f);
        u2 = u1;
    } else {
        u0.x = tW2[(cbase + 0) * 3]; u0.y = tW2[(cbase + 1) * 3];
        u0.z = tW2[(cbase + 2) * 3]; u0.w = tW2[(cbase + 3) * 3];
        u1.x = tW2[(cbase + 0) * 3 + 1]; u1.y = tW2[(cbase + 1) * 3 + 1];
        u1.z = tW2[(cbase + 2) * 3 + 1]; u1.w = tW2[(cbase + 3) * 3 + 1];
        u2.x = tW2[(cbase + 0) * 3 + 2]; u2.y = tW2[(cbase + 1) * 3 + 2];
        u2.z = tW2[(cbase + 2) * 3 + 2]; u2.w = tW2[(cbase + 3) * 3 + 2];
    }
    float sb2v = sb2[0];
    float tb0 = tb2[0], tb1v = tb2[1], tb2v = tb2[2];
    const float4* C4 = (const float4*)g_C;
    float* outT = out + (E_ + G_);

    int gw = (blockIdx.x * blockDim.x + threadIdx.x) >> 5;
    int nw = (gridDim.x * blockDim.x) >> 5;

    int e = gw;
    float4 f, c;
    if (e < E_) {
        int t = targets[e];
        f = feats4[e];
        c = C4[(size_t)t * 32 + lane];
    }
    while (e < E_) {
        int e2 = e + nw;
        float4 f2, c2;
        if (e2 < E_) {
            int t2 = targets[e2];
            f2 = feats4[e2];
            c2 = C4[(size_t)t2 * 32 + lane];
        }
        float dv = sdt[(int)fminf(f.x, 9.0f)];
        float hx = fmaxf(fmaf(dv, w512.x, fmaf(f.y, w513.x, fmaf(f.z, w514.x, fmaf(f.w, w515.x, c.x)))), 0.f);
        float hy = fmaxf(fmaf(dv, w512.y, fmaf(f.y, w513.y, fmaf(f.z, w514.y, fmaf(f.w, w515.y, c.y)))), 0.f);
        float hz = fmaxf(fmaf(dv, w512.z, fmaf(f.y, w513.z, fmaf(f.z, w514.z, fmaf(f.w, w515.z, c.z)))), 0.f);
        float hw = fmaxf(fmaf(dv, w512.w, fmaf(f.y, w513.w, fmaf(f.z, w514.w, fmaf(f.w, w515.w, c.w)))), 0.f);
        float v0 = fmaf(hx, u0.x, fmaf(hy, u0.y, fmaf(hz, u0.z, hw * u0.w)));
        float v1 = fmaf(hx, u1.x, fmaf(hy, u1.y, fmaf(hz, u1.z, hw * u1.w)));
        float v2 = fmaf(hx, u2.x, fmaf(hy, u2.y, fmaf(hz, u2.z, hw * u2.w)));
        float p = isS ? v0 : v1;
        float q = __shfl_xor_sync(0xffffffffu, v0, 16);
        q = isS ? q : v2;
#pragma unroll
        for (int o = 1; o <= 8; o <<= 1) {
            p += __shfl_xor_sync(0xffffffffu, p, o);
            q += __shfl_xor_sync(0xffffffffu, q, o);
        }
        if (lane == 0) {
            out[e] = p + sb2v;          // scorer logit
            outT[3 * e] = q + tb0;      // type logit 0
        }
        if (lane == 16) {
            outT[3 * e + 1] = p + tb1v; // type logit 1
            outT[3 * e + 2] = q + tb2v; // type logit 2
        }
        e = e2; f = f2; c = c2;
    }
}

// ---------------------------------------------------------------------------
extern "C" void kernel_launch(void* const* d_in, const int* in_sizes, int n_in,
                              void* d_out, int out_size) {
    const float* imr     = (const float*)d_in[0];
    const float* pgr     = (const float*)d_in[1];
    const float* nodes   = (const float*)d_in[2];
    const int*   focus   = (const int*)d_in[3];
    const int*   n2g     = (const int*)d_in[4];
    const int*   targets = (const int*)d_in[5];
    const float* feats   = (const float*)d_in[6];
    int p = 7;
    if (p < n_in && in_sizes[p] == 1) p++;  // skip num_graphs_in_batch scalar if present
    const float* dist_table = (const float*)d_in[p++];  // [10]
    const float* no_more    = (const float*)d_in[p++];  // [132]
    const float* sW1 = (const float*)d_in[p++];         // [516,64]
    const float* sb1 = (const float*)d_in[p++];         // [64]
    const float* sW2 = (const float*)d_in[p++];         // [64]
    const float* sb2 = (const float*)d_in[p++];         // [1]
    const float* tW1 = (const float*)d_in[p++];         // [516,64]
    const float* tb1 = (const float*)d_in[p++];         // [64]
    const float* tW2 = (const float*)d_in[p++];         // [64,3]
    const float* tb2 = (const float*)d_in[p++];         // [3]
    float* out = (float*)d_out;

    kP<<<1, 256>>>(no_more, sW1);
    kA<<<G_ / 8, 128>>>(imr, pgr, nodes, focus, sW1, sb1, tW1, tb1, sW2, sb2, out);
    kB<<<N_ / 128, 512>>>(nodes, sW1, tW1, n2g);
    kE<<<1184, 256>>>(targets, (const float4*)feats, sW1, tW1, sW2, sb2, tW2, tb2,
                      dist_table, out);
}